// round 1
// baseline (speedup 1.0000x reference)
#include <cuda_runtime.h>
#include <float.h>
#include <math.h>

#define B_ 8
#define C_ 32
#define H_ 512
#define W_ 512
#define HW_ (H_*W_)

// Scratch (allocation-free rule: static __device__ arrays)
__device__ float g_fs[B_*C_*H_*W_];   // 256 MiB: conv1x1 output (pre-attention)
__device__ float g_cm[B_*H_*W_];      // channel max plane
__device__ float g_ca[B_*H_*W_];      // channel mean plane

__device__ __forceinline__ float fsigmoid(float z) {
    return 1.0f / (1.0f + __expf(-z));
}

// ---------------------------------------------------------------------------
// Kernel A: per 2x2 patch — patch max/avg pool -> gate -> fused (concat+1x1)
// out[o] = sum_c x[c]*(gate[c]*w1[o,c] + w2[o,c]) + b[o]
// Also produces channel max / mean planes for the 7x7 attention conv.
// One thread per patch; block = one patch row (256 patches), grid = (256, B).
// ---------------------------------------------------------------------------
__global__ __launch_bounds__(256, 1)
void kernelA(const float* __restrict__ x,
             const float* __restrict__ mlp_w,
             const float* __restrict__ mlp_b,
             const float* __restrict__ conv_w,
             const float* __restrict__ conv_b)
{
    __shared__ __align__(16) float s_w1[32][32];  // [c][o] = conv_w[o,c]
    __shared__ __align__(16) float s_w2[32][32];  // [c][o] = conv_w[o,32+c]
    __shared__ float s_b[32];

    const int tid = threadIdx.x;
    for (int i = tid; i < 1024; i += 256) {
        int o = i & 31, c = i >> 5;
        s_w1[c][o] = conv_w[o * 64 + c];
        s_w2[c][o] = conv_w[o * 64 + 32 + c];
    }
    if (tid < 32) s_b[tid] = conv_b[tid];
    __syncthreads();

    const int hp = blockIdx.x;   // patch row 0..255
    const int b  = blockIdx.y;   // batch
    const int wp = tid;          // patch col 0..255

    const float2* __restrict__ x2 = (const float2*)x;
    const float mw  = __ldg(mlp_w);
    const float mb2 = 2.0f * __ldg(mlp_b);

    float acc0[32], acc1[32], acc2[32], acc3[32];
#pragma unroll
    for (int o = 0; o < 32; o++) { acc0[o] = 0.f; acc1[o] = 0.f; acc2[o] = 0.f; acc3[o] = 0.f; }

#pragma unroll 2
    for (int c = 0; c < 32; c++) {
        unsigned p = (((unsigned)(b * 32 + c)) * 512u + 2u * hp) * 256u + wp;
        float2 r0 = x2[p];
        float2 r1 = x2[p + 256];
        float m = fmaxf(fmaxf(r0.x, r0.y), fmaxf(r1.x, r1.y));
        float a = 0.25f * ((r0.x + r0.y) + (r1.x + r1.y));
        float g = fsigmoid(fmaf(m + a, mw, mb2));
        const float4* __restrict__ w1r = (const float4*)s_w1[c];
        const float4* __restrict__ w2r = (const float4*)s_w2[c];
#pragma unroll
        for (int o4 = 0; o4 < 8; o4++) {
            float4 wa = w1r[o4];
            float4 wb = w2r[o4];
            float we;
            int o = o4 * 4;
            we = fmaf(g, wa.x, wb.x);
            acc0[o+0] = fmaf(r0.x, we, acc0[o+0]);
            acc1[o+0] = fmaf(r0.y, we, acc1[o+0]);
            acc2[o+0] = fmaf(r1.x, we, acc2[o+0]);
            acc3[o+0] = fmaf(r1.y, we, acc3[o+0]);
            we = fmaf(g, wa.y, wb.y);
            acc0[o+1] = fmaf(r0.x, we, acc0[o+1]);
            acc1[o+1] = fmaf(r0.y, we, acc1[o+1]);
            acc2[o+1] = fmaf(r1.x, we, acc2[o+1]);
            acc3[o+1] = fmaf(r1.y, we, acc3[o+1]);
            we = fmaf(g, wa.z, wb.z);
            acc0[o+2] = fmaf(r0.x, we, acc0[o+2]);
            acc1[o+2] = fmaf(r0.y, we, acc1[o+2]);
            acc2[o+2] = fmaf(r1.x, we, acc2[o+2]);
            acc3[o+2] = fmaf(r1.y, we, acc3[o+2]);
            we = fmaf(g, wa.w, wb.w);
            acc0[o+3] = fmaf(r0.x, we, acc0[o+3]);
            acc1[o+3] = fmaf(r0.y, we, acc1[o+3]);
            acc2[o+3] = fmaf(r1.x, we, acc2[o+3]);
            acc3[o+3] = fmaf(r1.y, we, acc3[o+3]);
        }
    }

    // bias + channel stats
    float mx0 = -FLT_MAX, mx1 = -FLT_MAX, mx2 = -FLT_MAX, mx3 = -FLT_MAX;
    float s0 = 0.f, s1 = 0.f, s2 = 0.f, s3 = 0.f;
#pragma unroll
    for (int o = 0; o < 32; o++) {
        float bo = s_b[o];
        acc0[o] += bo; acc1[o] += bo; acc2[o] += bo; acc3[o] += bo;
        mx0 = fmaxf(mx0, acc0[o]); s0 += acc0[o];
        mx1 = fmaxf(mx1, acc1[o]); s1 += acc1[o];
        mx2 = fmaxf(mx2, acc2[o]); s2 += acc2[o];
        mx3 = fmaxf(mx3, acc3[o]); s3 += acc3[o];
    }

    float2* __restrict__ fs2 = (float2*)g_fs;
#pragma unroll
    for (int o = 0; o < 32; o++) {
        unsigned p = (((unsigned)(b * 32 + o)) * 512u + 2u * hp) * 256u + wp;
        fs2[p]       = make_float2(acc0[o], acc1[o]);
        fs2[p + 256] = make_float2(acc2[o], acc3[o]);
    }
    unsigned q = (((unsigned)b) * 512u + 2u * hp) * 256u + wp;
    ((float2*)g_cm)[q]       = make_float2(mx0, mx1);
    ((float2*)g_cm)[q + 256] = make_float2(mx2, mx3);
    const float inv = 1.0f / 32.0f;
    ((float2*)g_ca)[q]       = make_float2(s0 * inv, s1 * inv);
    ((float2*)g_ca)[q + 256] = make_float2(s2 * inv, s3 * inv);
}

// ---------------------------------------------------------------------------
// Kernel B: 7x7 SAME conv on [cm;ca] (2->32 ch), sigmoid, multiply by fs.
// Tile 64x16 pixels + 3px halo in smem; thread = 1 pixel column x 4 rows.
// ---------------------------------------------------------------------------
#define TW 64
#define TH 16

__global__ __launch_bounds__(256, 1)
void kernelB(const float* __restrict__ cow,
             const float* __restrict__ cob,
             float* __restrict__ out)
{
    __shared__ __align__(16) float s_in[2][TH + 6][TW + 6];
    __shared__ __align__(16) float s_w[98][32];   // [tap][o], tap = j*49+dy*7+dx
    __shared__ float s_b[32];

    const int tid = threadIdx.x;
    const int b   = blockIdx.z;
    const int tyb = blockIdx.y * TH;
    const int txb = blockIdx.x * TW;

    // weights: convout_w layout (o, j, 7, 7) -> [tap][o]
    for (int i = tid; i < 98 * 32; i += 256) {
        int o = i & 31, tap = i >> 5;
        s_w[tap][o] = cow[o * 98 + tap];
    }
    if (tid < 32) s_b[tid] = cob[tid];

    // input tile with halo, zero padding (SAME)
    for (int i = tid; i < 2 * (TH + 6) * (TW + 6); i += 256) {
        int plane = i / ((TH + 6) * (TW + 6));
        int rem   = i % ((TH + 6) * (TW + 6));
        int r  = rem / (TW + 6);
        int cc = rem % (TW + 6);
        int h = tyb - 3 + r;
        int w = txb - 3 + cc;
        float v = 0.f;
        if (h >= 0 && h < H_ && w >= 0 && w < W_) {
            const float* src = plane ? g_ca : g_cm;
            v = src[((unsigned)b * H_ + h) * W_ + w];
        }
        s_in[plane][r][cc] = v;
    }
    __syncthreads();

    const int tx  = tid & 63;   // 0..63
    const int ty0 = tid >> 6;   // 0..3

    for (int py = 0; py < 4; py++) {
        const int ty = ty0 * 4 + py;   // 0..15
        float acc[32];
#pragma unroll
        for (int o = 0; o < 32; o++) acc[o] = s_b[o];

        for (int j = 0; j < 2; j++) {
            for (int dy = 0; dy < 7; dy++) {
                const float* __restrict__ row = &s_in[j][ty + dy][tx];
#pragma unroll
                for (int dx = 0; dx < 7; dx++) {
                    float v = row[dx];
                    const float4* __restrict__ w4 = (const float4*)&s_w[j * 49 + dy * 7 + dx][0];
#pragma unroll
                    for (int o4 = 0; o4 < 8; o4++) {
                        float4 w = w4[o4];
                        acc[o4*4+0] = fmaf(v, w.x, acc[o4*4+0]);
                        acc[o4*4+1] = fmaf(v, w.y, acc[o4*4+1]);
                        acc[o4*4+2] = fmaf(v, w.z, acc[o4*4+2]);
                        acc[o4*4+3] = fmaf(v, w.w, acc[o4*4+3]);
                    }
                }
            }
        }

        const int h = tyb + ty;
        const int w = txb + tx;
        unsigned fbase = (((unsigned)b * 32) * 512u + h) * 512u + w;
#pragma unroll
        for (int o = 0; o < 32; o++) {
            float f = g_fs[fbase + (unsigned)o * (unsigned)HW_];
            out[fbase + (unsigned)o * (unsigned)HW_] = fsigmoid(acc[o]) * f;
        }
    }
}

extern "C" void kernel_launch(void* const* d_in, const int* in_sizes, int n_in,
                              void* d_out, int out_size)
{
    (void)in_sizes; (void)n_in; (void)out_size;
    const float* x      = (const float*)d_in[0];
    const float* mlp_w  = (const float*)d_in[1];
    const float* mlp_b  = (const float*)d_in[2];
    const float* conv_w = (const float*)d_in[3];
    const float* conv_b = (const float*)d_in[4];
    const float* cow    = (const float*)d_in[5];
    const float* cob    = (const float*)d_in[6];
    float* out = (float*)d_out;

    kernelA<<<dim3(256, 8), 256>>>(x, mlp_w, mlp_b, conv_w, conv_b);
    kernelB<<<dim3(W_ / TW, H_ / TH, 8), 256>>>(cow, cob, out);
}